// round 14
// baseline (speedup 1.0000x reference)
#include <cuda_runtime.h>
#include <cuda_bf16.h>
#include <cstdint>

// DifferentiableTopKSelector == per-row hard top-32 mask of raw scores
// (straight-through estimator is value-identical to hard_mask; `u` is dead).
//
// Round 14 (= R13 resubmit after infra failure): split the mixed R/W stream
// into two pure streams.
//   k1: pure zero-fill of the 128 MB output (write-only, streaming).
//   k2: pure read of scores + scatter of 32 ones/row (read-only + 512 KB).
// Same total bytes; pure streams avoid DRAM R/W turnaround and L1tex
// read/write contention that capped the fused kernel at ~5.3 TB/s.
// k2 keeps the R12 machinery: front-batched LDG.128, guess-threshold
// candidates, warp-aggregated push (1 atomic/warp), exact stable rank on
// 64-bit composite keys (jax.lax.top_k tie-break), serial exact fallback.

static constexpr int COLS = 8192;
static constexpr int NT   = 512;
static constexpr int VPT  = COLS / 4 / NT;   // 4 float4 per thread
static constexpr int CAP  = 256;
static constexpr int KSEL = 32;
#define GUESS 2.3f

// ---------------- kernel 1: pure streaming zero-fill ----------------
static constexpr int ZNT   = 256;
static constexpr int ZGRID = 1184;           // 8 CTAs/SM * 148 SMs

__global__ void __launch_bounds__(ZNT)
zero_kernel(float4* __restrict__ out4, int total4) {
    const float4 z = make_float4(0.f, 0.f, 0.f, 0.f);
    const int step = ZNT * gridDim.x;
    for (int i = blockIdx.x * ZNT + threadIdx.x; i < total4; i += step)
        __stcs(out4 + i, z);
}

// ---------------- kernel 2: read + top-32 scatter ----------------
__device__ __forceinline__ unsigned long long pack_key(float v, unsigned idx) {
    // v > GUESS > 0: float bits compare as unsigned. Inverted index makes
    // larger composite == (larger value, then smaller index).
    return ((unsigned long long)__float_as_uint(v) << 32)
         | (unsigned long long)(COLS - 1u - idx);
}

__global__ void __launch_bounds__(NT, 4)
topk_scatter_kernel(const float* __restrict__ scores, float* __restrict__ out) {
    __shared__ unsigned long long cand[CAP];   // 2 KB
    __shared__ int s_cnt;

    const int t = threadIdx.x;
    if (t == 0) s_cnt = 0;                     // visible after 1st barrier

    const size_t rowoff = (size_t)blockIdx.x * (size_t)COLS;
    const float4* in4 = (const float4*)(scores + rowoff);

    // ---- front-batched loads, issue at cycle 0 (no prior barrier) ----
    float4 v[VPT];
    #pragma unroll
    for (int it = 0; it < VPT; ++it)
        v[it] = __ldcs(in4 + t + it * NT);

    // ---- per-lane hit count (registers only) ----
    unsigned n = 0;
    #pragma unroll
    for (int it = 0; it < VPT; ++it)
        n += (v[it].x > GUESS) + (v[it].y > GUESS)
           + (v[it].z > GUESS) + (v[it].w > GUESS);

    __syncthreads();     // orders s_cnt=0 before atomics

    // ---- warp-aggregated push: ONE shared atomic per warp ----
    unsigned incl = n;
    #pragma unroll
    for (int d = 1; d < 32; d <<= 1) {
        unsigned o = __shfl_up_sync(0xFFFFFFFFu, incl, d);
        if ((t & 31) >= d) incl += o;
    }
    const unsigned total = __shfl_sync(0xFFFFFFFFu, incl, 31);
    if (total) {
        unsigned base = 0;
        if ((t & 31) == 31) base = (unsigned)atomicAdd(&s_cnt, (int)total);
        base = __shfl_sync(0xFFFFFFFFu, base, 31);
        if (n) {
            unsigned pos = base + incl - n;
            #pragma unroll
            for (int it = 0; it < VPT; ++it) {
                const unsigned bb = (unsigned)((t + it * NT) * 4);
                if (v[it].x > GUESS && pos < CAP) cand[pos++] = pack_key(v[it].x, bb + 0u);
                if (v[it].y > GUESS && pos < CAP) cand[pos++] = pack_key(v[it].y, bb + 1u);
                if (v[it].z > GUESS && pos < CAP) cand[pos++] = pack_key(v[it].z, bb + 2u);
                if (v[it].w > GUESS && pos < CAP) cand[pos++] = pack_key(v[it].w, bb + 3u);
            }
        }
    }
    __syncthreads();

    const int cnt = s_cnt;

    if (cnt >= KSEL && cnt <= CAP) {
        // ---- exact stable rank among candidates; scatter the 32 ones ----
        if (t < cnt) {
            const unsigned long long ci = cand[t];
            int r = 0;
            #pragma unroll 4
            for (int j = 0; j < cnt; ++j)
                r += (cand[j] > ci);                 // LDS.64 broadcast
            if (r < KSEL) {
                unsigned idx = COLS - 1u - (unsigned)(ci & 0xFFFFFFFFull);
                out[rowoff + idx] = 1.0f;
            }
        }
    } else if (t == 0) {
        // ---- exact serial fallback (correctness guard; 6-sigma event) ----
        float    bk[KSEL];
        unsigned bi[KSEL];
        #pragma unroll
        for (int i = 0; i < KSEL; ++i) { bk[i] = -INFINITY; bi[i] = 0u; }
        const float* rowp = scores + rowoff;
        for (int i = 0; i < COLS; ++i) {
            float vv = rowp[i];
            if (vv > bk[KSEL - 1]) {                 // strict > == stable
                int p = KSEL - 1;
                while (p > 0 && vv > bk[p - 1]) {
                    bk[p] = bk[p - 1]; bi[p] = bi[p - 1]; --p;
                }
                bk[p] = vv; bi[p] = (unsigned)i;
            }
        }
        for (int i = 0; i < KSEL; ++i)
            out[rowoff + bi[i]] = 1.0f;
    }
}

extern "C" void kernel_launch(void* const* d_in, const int* in_sizes, int n_in,
                              void* d_out, int out_size) {
    const float* scores = (const float*)d_in[0];   // (4096, 8192) fp32
    // d_in[1] (u) is mathematically dead: output == hard top-k mask of scores.
    float* out = (float*)d_out;
    const int rows = out_size / COLS;              // 4096

    // k1: pure write stream (zeros). k2: pure read stream + 32 ones/row.
    // Same-stream ordering guarantees the scatter lands after the fill.
    const int total4 = out_size / 4;               // float4 count
    zero_kernel<<<ZGRID, ZNT>>>((float4*)out, total4);
    topk_scatter_kernel<<<rows, NT>>>(scores, out);
}

// round 15
// speedup vs baseline: 1.3041x; 1.3041x over previous
#include <cuda_runtime.h>
#include <cuda_bf16.h>
#include <cstdint>

// DifferentiableTopKSelector == per-row hard top-32 mask of raw scores
// (straight-through estimator is value-identical to hard_mask; `u` is dead).
//
// Round 15: fused R12 skeleton (split streams measured slower), with the
// rank phase — the largest issue block — cut ~2.3x via a tighter primary
// threshold (2.45 -> ~58 candidates) made safe by a PARALLEL tier-2
// re-detect from live registers at threshold 1.9 (~235 candidates) when the
// primary misfires (<1%/run), plus a serial tier-3 guard for arbitrary data.
// REDUX warp total (1 instr), scan only in warps with hits, unguarded push
// after a single per-warp capacity check.

static constexpr int COLS = 8192;
static constexpr int NT   = 512;
static constexpr int VPT  = COLS / 4 / NT;   // 4 float4 per thread
static constexpr int CAP  = 384;
static constexpr int KSEL = 32;
#define GUESS1 2.45f
#define GUESS2 1.90f

__device__ __forceinline__ unsigned long long pack_key(float v, unsigned idx) {
    // v > th > 0: float bits compare as unsigned. Inverted index makes
    // larger composite == (larger value, then smaller index) — exactly
    // jax.lax.top_k's stable tie-break.
    return ((unsigned long long)__float_as_uint(v) << 32)
         | (unsigned long long)(COLS - 1u - idx);
}

__global__ void __launch_bounds__(NT, 4)
topk_mask_kernel(const float* __restrict__ scores, float* __restrict__ out) {
    __shared__ unsigned long long cand[CAP];   // 3 KB
    __shared__ int s_cnt;

    const int t = threadIdx.x;
    if (t == 0) s_cnt = 0;                     // ordered by barrier below

    const size_t rowoff = (size_t)blockIdx.x * (size_t)COLS;
    const float4* in4  = (const float4*)(scores + rowoff);
    float4*       out4 = (float4*)(out + rowoff);
    const float4  zero4 = make_float4(0.f, 0.f, 0.f, 0.f);

    // ---- loads issue at cycle 0, back-to-back (front-batched MLP) ----
    float4 v[VPT];
    #pragma unroll
    for (int it = 0; it < VPT; ++it)
        v[it] = __ldcs(in4 + t + it * NT);

    // ---- zero fill, independent of load results ----
    #pragma unroll
    for (int it = 0; it < VPT; ++it)
        __stcs(out4 + t + it * NT, zero4);

    // ---- tiered detect + rank (tier 0: 2.45, tier 1: 1.9) ----
    bool done = false;
    float th = GUESS1;

    #pragma unroll 1
    for (int tier = 0; tier < 2 && !done; ++tier) {
        // per-lane hit count on registers
        unsigned n = 0;
        #pragma unroll
        for (int it = 0; it < VPT; ++it)
            n += (v[it].x > th) + (v[it].y > th)
               + (v[it].z > th) + (v[it].w > th);

        __syncthreads();                 // s_cnt reset visible before atomics

        const unsigned total = __reduce_add_sync(0xFFFFFFFFu, n);   // REDUX
        if (total) {
            unsigned incl = n;           // inclusive scan (only warps w/ hits)
            #pragma unroll
            for (int d = 1; d < 32; d <<= 1) {
                unsigned o = __shfl_up_sync(0xFFFFFFFFu, incl, d);
                if ((t & 31) >= d) incl += o;
            }
            unsigned base = 0;
            if ((t & 31) == 31) base = (unsigned)atomicAdd(&s_cnt, (int)total);
            base = __shfl_sync(0xFFFFFFFFu, base, 31);
            if (n && base + total <= CAP) {      // one capacity check per warp
                unsigned pos = base + incl - n;  // unguarded pushes
                #pragma unroll
                for (int it = 0; it < VPT; ++it) {
                    const unsigned bb = (unsigned)((t + it * NT) * 4);
                    if (v[it].x > th) cand[pos++] = pack_key(v[it].x, bb + 0u);
                    if (v[it].y > th) cand[pos++] = pack_key(v[it].y, bb + 1u);
                    if (v[it].z > th) cand[pos++] = pack_key(v[it].z, bb + 2u);
                    if (v[it].w > th) cand[pos++] = pack_key(v[it].w, bb + 3u);
                }
            }
        }
        __syncthreads();
        const int cnt = s_cnt;

        if (cnt >= KSEL && cnt <= CAP) {
            // ---- exact stable rank; scatter the 32 ones ----
            if (t < cnt) {
                const unsigned long long ci = cand[t];
                int r = 0;
                for (int j = 0; j < cnt; ++j)
                    r += (cand[j] > ci);             // LDS.64 broadcast
                if (r < KSEL) {
                    unsigned idx = COLS - 1u - (unsigned)(ci & 0xFFFFFFFFull);
                    out[rowoff + idx] = 1.0f;
                }
            }
            done = true;
        } else {
            // tier misfired (rare): reset and retry with lower threshold
            __syncthreads();
            if (t == 0) s_cnt = 0;
            th = GUESS2;
            // s_cnt reset ordered by the barrier at the top of next tier
        }
    }

    if (!done && t == 0) {
        // ---- tier 3: exact serial guard for arbitrary inputs ----
        float    bk[KSEL];
        unsigned bi[KSEL];
        #pragma unroll
        for (int i = 0; i < KSEL; ++i) { bk[i] = -INFINITY; bi[i] = 0u; }
        const float* rowp = scores + rowoff;
        for (int i = 0; i < COLS; ++i) {
            float vv = rowp[i];
            if (vv > bk[KSEL - 1]) {                 // strict > == stable
                int p = KSEL - 1;
                while (p > 0 && vv > bk[p - 1]) {
                    bk[p] = bk[p - 1]; bi[p] = bi[p - 1]; --p;
                }
                bk[p] = vv; bi[p] = (unsigned)i;
            }
        }
        for (int i = 0; i < KSEL; ++i)
            out[rowoff + bi[i]] = 1.0f;
    }
}

extern "C" void kernel_launch(void* const* d_in, const int* in_sizes, int n_in,
                              void* d_out, int out_size) {
    const float* scores = (const float*)d_in[0];   // (4096, 8192) fp32
    // d_in[1] (u) is mathematically dead: output == hard top-k mask of scores.
    float* out = (float*)d_out;
    const int rows = out_size / COLS;              // 4096
    topk_mask_kernel<<<rows, NT>>>(scores, out);
}